// round 15
// baseline (speedup 1.0000x reference)
#include <cuda_runtime.h>
#include <cuda_bf16.h>
#include <cuda_fp16.h>
#include <cstdint>

#define CC    256
#define CQ    64
#define NPIX  4096
#define NPAIR 4
#define LOG2E 1.4426950408889634f

// ---------------- helpers ----------------
__device__ __forceinline__ uint32_t smem_u32(const void* p) {
    uint32_t a;
    asm("{ .reg .u64 t; cvta.to.shared.u64 t, %1; cvt.u32.u64 %0, t; }" : "=r"(a) : "l"(p));
    return a;
}

__device__ __forceinline__ void cp16(uint32_t s, const void* g) {
    asm volatile("cp.async.cg.shared.global [%0], [%1], 16;" :: "r"(s), "l"(g) : "memory");
}
#define CP_COMMIT()  asm volatile("cp.async.commit_group;" ::: "memory")
#define CP_WAIT(N)   asm volatile("cp.async.wait_group %0;" :: "n"(N) : "memory")

// ldmatrix x4: four 8x8 b16 matrices -> 4 regs
__device__ __forceinline__ void ldsm4(uint32_t r[4], uint32_t addr) {
    asm volatile("ldmatrix.sync.aligned.m8n8.x4.shared.b16 {%0,%1,%2,%3}, [%4];"
        : "=r"(r[0]), "=r"(r[1]), "=r"(r[2]), "=r"(r[3]) : "r"(addr));
}

// m16n8k16 bf16 mma (S phase + proj)
__device__ __forceinline__ void mma16(float c[4], const uint32_t a[4], uint32_t b0, uint32_t b1) {
    asm volatile(
        "mma.sync.aligned.m16n8k16.row.col.f32.bf16.bf16.f32 "
        "{%0,%1,%2,%3}, {%4,%5,%6,%7}, {%8,%9}, {%0,%1,%2,%3};"
        : "+f"(c[0]), "+f"(c[1]), "+f"(c[2]), "+f"(c[3])
        : "r"(a[0]), "r"(a[1]), "r"(a[2]), "r"(a[3]), "r"(b0), "r"(b1));
}

// m16n8k16 fp16 mma (PV phase)
__device__ __forceinline__ void mma16f(float c[4], const uint32_t a[4], uint32_t b0, uint32_t b1) {
    asm volatile(
        "mma.sync.aligned.m16n8k16.row.col.f32.f16.f16.f32 "
        "{%0,%1,%2,%3}, {%4,%5,%6,%7}, {%8,%9}, {%0,%1,%2,%3};"
        : "+f"(c[0]), "+f"(c[1]), "+f"(c[2]), "+f"(c[3])
        : "r"(a[0]), "r"(a[1]), "r"(a[2]), "r"(a[3]), "r"(b0), "r"(b1));
}

__device__ __forceinline__ uint32_t pack_bf16(float a, float b) {
    __nv_bfloat16 h0 = __float2bfloat16(a), h1 = __float2bfloat16(b);
    uint16_t u0 = *(uint16_t*)&h0, u1 = *(uint16_t*)&h1;
    return ((uint32_t)u1 << 16) | u0;
}

// ---------------- scratch ----------------
__device__ float g_Bias[2][384];
__device__ __nv_bfloat16 g_Wh[2][384][CC];
__device__ __nv_bfloat16 g_Wl[2][384][CC];
__device__ __nv_bfloat16 g_Xh[NPAIR][NPIX][CC];
__device__ __nv_bfloat16 g_Xl[NPAIR][NPIX][CC];
__device__ __nv_bfloat16 g_Qh[NPAIR][NPIX][CQ];   // scaled by log2(e)
__device__ __nv_bfloat16 g_Ql[NPAIR][NPIX][CQ];
__device__ __nv_bfloat16 g_Kh[NPAIR][NPIX][CQ];
__device__ __nv_bfloat16 g_Kl[NPAIR][NPIX][CQ];
__device__ __half g_V[NPAIR][CC][NPIX];           // channel-major fp16 V

// ---------------------------------------------------------------------------
// Merged prep (weights split) + convert (input transpose/split): independent
// work partitioned by blockIdx so both run concurrently in ONE launch.
//   blocks [0, 1024)    : convert_x work  (nb 64, cb 4, p 4)
//   blocks [1024, 1792) : prep_weights work (o 384, s 2)
// ---------------------------------------------------------------------------
__global__ __launch_bounds__(256) void prep_and_convert(
    const float* __restrict__ in1, const float* __restrict__ in2,
    const float* __restrict__ q1w, const float* __restrict__ q1b,
    const float* __restrict__ k1w, const float* __restrict__ k1b,
    const float* __restrict__ v1w, const float* __restrict__ v1b,
    const float* __restrict__ q2w, const float* __restrict__ q2b,
    const float* __restrict__ k2w, const float* __restrict__ k2b,
    const float* __restrict__ v2w, const float* __restrict__ v2b)
{
    __shared__ float t[64][65];
    int bx = blockIdx.x;
    int tid = threadIdx.x;

    if (bx >= 1024) {
        // ---- prep_weights part ----
        int idx = bx - 1024;
        int o = idx & 383, s = idx >> 9;   // idx: o in [0,384) for s=0, o+512? no:
        // 768 blocks: s = idx / 384, o = idx % 384
        s = idx / 384; o = idx - s * 384;
        const float* w; const float* bsrc; int row;
        if (o < 64)       { w = s ? q2w : q1w; bsrc = s ? q2b : q1b; row = o; }
        else if (o < 128) { w = s ? k2w : k1w; bsrc = s ? k2b : k1b; row = o - 64; }
        else              { w = s ? v2w : v1w; bsrc = s ? v2b : v1b; row = o - 128; }
        float v = w[row * CC + tid];
        __nv_bfloat16 h = __float2bfloat16(v);
        g_Wh[s][o][tid] = h;
        g_Wl[s][o][tid] = __float2bfloat16(v - __bfloat162float(h));
        if (tid == 0) g_Bias[s][o] = bsrc[row];
        return;
    }

    // ---- convert_x part ----
    int nb = bx & 63, cb4 = (bx >> 6) & 3, p = bx >> 8;
    int s = p >> 1, b = p & 1;
    const float* x = (s ? in2 : in1) + (size_t)b * CC * NPIX;
    int n0 = nb * 64, c0 = cb4 * 64;

    #pragma unroll
    for (int i = 0; i < 4; i++) {
        int m = tid + i * 256;
        int c = m >> 4, nn = (m & 15) << 2;
        float4 v = *(const float4*)&x[(size_t)(c0 + c) * NPIX + n0 + nn];
        t[c][nn] = v.x; t[c][nn + 1] = v.y; t[c][nn + 2] = v.z; t[c][nn + 3] = v.w;
    }
    __syncthreads();

    int n = tid >> 2, cb = (tid & 3) << 4;
    uint32_t hw[8], lw[8];
    #pragma unroll
    for (int j = 0; j < 8; j++) {
        float v0 = t[cb + 2 * j][n], v1 = t[cb + 2 * j + 1][n];
        __nv_bfloat16 h0 = __float2bfloat16(v0);
        __nv_bfloat16 h1 = __float2bfloat16(v1);
        float l0 = v0 - __bfloat162float(h0);
        float l1 = v1 - __bfloat162float(h1);
        uint16_t a0 = *(uint16_t*)&h0, a1 = *(uint16_t*)&h1;
        hw[j] = ((uint32_t)a1 << 16) | a0;
        lw[j] = pack_bf16(l0, l1);
    }
    uint4* dh = (uint4*)&g_Xh[p][n0 + n][c0 + cb];
    uint4* dl = (uint4*)&g_Xl[p][n0 + n][c0 + cb];
    dh[0] = make_uint4(hw[0], hw[1], hw[2], hw[3]);
    dh[1] = make_uint4(hw[4], hw[5], hw[6], hw[7]);
    dl[0] = make_uint4(lw[0], lw[1], lw[2], lw[3]);
    dl[1] = make_uint4(lw[4], lw[5], lw[6], lw[7]);
}

// ---------------------------------------------------------------------------
// Tensorized projection; Q epilogue pre-scales by log2(e) for base-2 softmax.
// ---------------------------------------------------------------------------
#define PJS 144u
#define PA_H 0u
#define PA_L 18432u
#define PB_H 36864u
#define PB_L 55296u
#define PSTAGE 73728u
#define POFF_BIAS 147456u
#define PSMEM 147968u

__global__ __launch_bounds__(256, 1) void proj_mma()
{
    extern __shared__ __align__(16) char psm[];
    uint32_t sb = smem_u32(psm);
    float* bias = (float*)(psm + POFF_BIAS);
    int tid = threadIdx.x;
    int p = blockIdx.z, s = p >> 1;
    int n0 = blockIdx.x * 128, o0 = blockIdx.y * 128;
    int warp = tid >> 5, lane = tid & 31;
    int wm = warp >> 1, wn = warp & 1;
    int r4 = lane >> 2, c4 = lane & 3;

    if (tid < 128) bias[tid] = g_Bias[s][o0 + tid];

    auto issue = [&](int kc) {
        uint32_t st = sb + (uint32_t)(kc & 1) * PSTAGE;
        int k0 = kc * 64;
        #pragma unroll
        for (int i = 0; i < 4; i++) {
            int m = tid + i * 256;
            int r = m >> 3, j = m & 7;
            uint32_t off = (uint32_t)r * PJS + (uint32_t)j * 16u;
            cp16(st + PA_H + off, &g_Xh[p][n0 + r][k0 + j * 8]);
            cp16(st + PA_L + off, &g_Xl[p][n0 + r][k0 + j * 8]);
            cp16(st + PB_H + off, &g_Wh[s][o0 + r][k0 + j * 8]);
            cp16(st + PB_L + off, &g_Wl[s][o0 + r][k0 + j * 8]);
        }
        CP_COMMIT();
    };
    issue(0);
    issue(1);

    float cS[2][8][4] = {};

    for (int kc = 0; kc < 4; kc++) {
        CP_WAIT(1);
        __syncthreads();
        const char* st = psm + (kc & 1) * PSTAGE;

        #pragma unroll
        for (int kt = 0; kt < 4; kt++) {
            int kb = kt * 32 + c4 * 4;
            uint32_t ah[2][4], al[2][4];
            #pragma unroll
            for (int mt = 0; mt < 2; mt++) {
                int r = wm * 32 + mt * 16 + r4;
                const char* a_h = st + PA_H + r * PJS + kb;
                const char* a_l = st + PA_L + r * PJS + kb;
                ah[mt][0] = *(const uint32_t*)a_h;
                ah[mt][1] = *(const uint32_t*)(a_h + 8 * PJS);
                ah[mt][2] = *(const uint32_t*)(a_h + 16);
                ah[mt][3] = *(const uint32_t*)(a_h + 8 * PJS + 16);
                al[mt][0] = *(const uint32_t*)a_l;
                al[mt][1] = *(const uint32_t*)(a_l + 8 * PJS);
                al[mt][2] = *(const uint32_t*)(a_l + 16);
                al[mt][3] = *(const uint32_t*)(a_l + 8 * PJS + 16);
            }
            #pragma unroll
            for (int nt = 0; nt < 8; nt++) {
                int o = wn * 64 + nt * 8 + r4;
                const char* b_h = st + PB_H + o * PJS + kb;
                const char* b_l = st + PB_L + o * PJS + kb;
                uint32_t bh0 = *(const uint32_t*)b_h;
                uint32_t bh1 = *(const uint32_t*)(b_h + 16);
                uint32_t bl0 = *(const uint32_t*)b_l;
                uint32_t bl1 = *(const uint32_t*)(b_l + 16);
                #pragma unroll
                for (int mt = 0; mt < 2; mt++) {
                    mma16(cS[mt][nt], ah[mt], bh0, bh1);
                    mma16(cS[mt][nt], al[mt], bh0, bh1);
                    mma16(cS[mt][nt], ah[mt], bl0, bl1);
                }
            }
        }
        __syncthreads();
        if (kc < 2) issue(kc + 2);
    }

    #pragma unroll
    for (int mt = 0; mt < 2; mt++) {
        int n_lo = n0 + wm * 32 + mt * 16 + r4;
        int n_hi = n_lo + 8;
        #pragma unroll
        for (int nt = 0; nt < 8; nt++) {
            int ol = wn * 64 + nt * 8 + 2 * c4;
            int og = o0 + ol;
            float b0 = bias[ol], b1 = bias[ol + 1];
            float y00 = cS[mt][nt][0] + b0, y01 = cS[mt][nt][1] + b1;
            float y10 = cS[mt][nt][2] + b0, y11 = cS[mt][nt][3] + b1;
            if (og < 64) {
                y00 *= LOG2E; y01 *= LOG2E; y10 *= LOG2E; y11 *= LOG2E;
                __nv_bfloat16 h00 = __float2bfloat16(y00), h01 = __float2bfloat16(y01);
                __nv_bfloat16 h10 = __float2bfloat16(y10), h11 = __float2bfloat16(y11);
                uint16_t u00 = *(uint16_t*)&h00, u01 = *(uint16_t*)&h01;
                uint16_t u10 = *(uint16_t*)&h10, u11 = *(uint16_t*)&h11;
                *(uint32_t*)&g_Qh[p][n_lo][og] = ((uint32_t)u01 << 16) | u00;
                *(uint32_t*)&g_Qh[p][n_hi][og] = ((uint32_t)u11 << 16) | u10;
                *(uint32_t*)&g_Ql[p][n_lo][og] =
                    pack_bf16(y00 - __bfloat162float(h00), y01 - __bfloat162float(h01));
                *(uint32_t*)&g_Ql[p][n_hi][og] =
                    pack_bf16(y10 - __bfloat162float(h10), y11 - __bfloat162float(h11));
            } else if (og < 128) {
                int oo = og - 64;
                __nv_bfloat16 h00 = __float2bfloat16(y00), h01 = __float2bfloat16(y01);
                __nv_bfloat16 h10 = __float2bfloat16(y10), h11 = __float2bfloat16(y11);
                uint16_t u00 = *(uint16_t*)&h00, u01 = *(uint16_t*)&h01;
                uint16_t u10 = *(uint16_t*)&h10, u11 = *(uint16_t*)&h11;
                *(uint32_t*)&g_Kh[p][n_lo][oo] = ((uint32_t)u01 << 16) | u00;
                *(uint32_t*)&g_Kh[p][n_hi][oo] = ((uint32_t)u11 << 16) | u10;
                *(uint32_t*)&g_Kl[p][n_lo][oo] =
                    pack_bf16(y00 - __bfloat162float(h00), y01 - __bfloat162float(h01));
                *(uint32_t*)&g_Kl[p][n_hi][oo] =
                    pack_bf16(y10 - __bfloat162float(h10), y11 - __bfloat162float(h11));
            } else {
                int c = og - 128;
                g_V[p][c][n_lo]     = __float2half(y00);
                g_V[p][c + 1][n_lo] = __float2half(y01);
                g_V[p][c][n_hi]     = __float2half(y10);
                g_V[p][c + 1][n_hi] = __float2half(y11);
            }
        }
    }
}

// ---------------------------------------------------------------------------
// Flash attention: 128-row tiles, 8 warps (4M x 2N), 1 CTA/SM.
// ONE full-CTA barrier/tile + one PAIR barrier for pmax. K double-buffered,
// V triple-buffered. Base-2 softmax via h2exp2 (f16x2 MUFU).
// ---------------------------------------------------------------------------
#define QKSB 144
#define KBUFB 18432u
#define OFF_K   0u
#define VBUFB  36864u
#define OFF_V0  36864u
#define OFF_QH 147456u
#define OFF_QL 165888u
#define OFF_P  184320u
#define OFF_L  202752u
#define OFF_PM 203264u
#define SMEM_TOTAL 204288u

__global__ __launch_bounds__(256, 1)
void flash_attn(const float* __restrict__ in1, const float* __restrict__ in2,
                const float* __restrict__ gamma, float* __restrict__ out)
{
    extern __shared__ __align__(16) char smem[];
    float* lrow = (float*)(smem + OFF_L);
    float* pmax = (float*)(smem + OFF_PM);
    uint32_t sb = smem_u32(smem);

    int tid  = threadIdx.x;
    int p    = blockIdx.y;
    int i0   = blockIdx.x * 128;
    int warp = tid >> 5, lane = tid & 31;
    int wm = warp >> 1, wn = warp & 1;       // 4M x 2N
    int r4 = lane >> 2, c4 = lane & 3;
    int lm = lane >> 3, lr = lane & 7;
    int mrow = wm * 32;

    uint32_t aRow = (uint32_t)((lm & 1) * 8 + lr) * QKSB + (uint32_t)((lm >> 1) * 16);
    uint32_t bRow = (uint32_t)((lm >> 1) * 8 + lr) * QKSB + (uint32_t)((lm & 1) * 16);

    if (tid < 128) lrow[tid] = 0.f;

    // ---- prologue: load Q, K(0), V(0); wait; publish ----
    {
        #pragma unroll
        for (int i = 0; i < 8; i++) {
            int m = tid + i * 256;
            int r = (m & 1023) >> 3, j = m & 7;
            if (m < 1024)
                cp16(sb + OFF_QH + (uint32_t)(r * QKSB + j * 16), &g_Qh[p][i0 + r][j * 8]);
            else
                cp16(sb + OFF_QL + (uint32_t)(r * QKSB + j * 16), &g_Ql[p][i0 + r][j * 8]);
        }
        #pragma unroll
        for (int i = 0; i < 4; i++) {
            int m = tid + i * 256;
            int r = (m & 511) >> 3, j = m & 7;
            if (m < 512)
                cp16(sb + OFF_K + (uint32_t)(r * QKSB + j * 16), &g_Kh[p][r][j * 8]);
            else
                cp16(sb + OFF_K + 9216u + (uint32_t)(r * QKSB + j * 16), &g_Kl[p][r][j * 8]);
        }
        #pragma unroll
        for (int i = 0; i < 8; i++) {
            int m = tid + i * 256;
            int ch = m >> 3, j = m & 7;
            cp16(sb + OFF_V0 + (uint32_t)(ch * QKSB + j * 16), &g_V[p][ch][j * 8]);
        }
        CP_COMMIT();
        CP_WAIT(0);
        __syncthreads();
    }

    float O[2][16][4];
    #pragma unroll
    for (int mt = 0; mt < 2; mt++)
        #pragma unroll
        for (int nt = 0; nt < 16; nt++)
            #pragma unroll
            for (int i = 0; i < 4; i++) O[mt][nt][i] = 0.f;

    float lsum[2][2] = {};
    float m_run[2][2] = {{-1e30f, -1e30f}, {-1e30f, -1e30f}};

    int vc = 0;

    for (int jt = 0; jt < 64; jt++) {
        uint32_t kbase = sb + OFF_K  + (uint32_t)(jt & 1) * KBUFB;
        uint32_t vbase = sb + OFF_V0 + (uint32_t)vc * VBUFB;
        int vn = vc + 1; if (vn == 3) vn = 0;

        // ---- prefetch V(jt+1) into third buffer ----
        if (jt < 63) {
            int j0n = (jt + 1) << 6;
            uint32_t vdst = sb + OFF_V0 + (uint32_t)vn * VBUFB;
            #pragma unroll
            for (int i = 0; i < 8; i++) {
                int m = tid + i * 256;
                int ch = m >> 3, j = m & 7;
                cp16(vdst + (uint32_t)(ch * QKSB + j * 16), &g_V[p][ch][j0n + j * 8]);
            }
            CP_COMMIT();
        }

        // ---- S = QK^T: 3-term split-bf16 (ldmatrix); logits in log2 units ----
        float cS[2][4][4];
        #pragma unroll
        for (int mt = 0; mt < 2; mt++)
            #pragma unroll
            for (int nt = 0; nt < 4; nt++)
                #pragma unroll
                for (int i = 0; i < 4; i++) cS[mt][nt][i] = 0.f;

        #pragma unroll
        for (int kt = 0; kt < 4; kt++) {
            uint32_t kbyte = (uint32_t)kt * 32u;
            uint32_t ah[2][4], al[2][4];
            #pragma unroll
            for (int mt = 0; mt < 2; mt++) {
                uint32_t qaddr = sb + OFF_QH + (uint32_t)(mrow + mt * 16) * QKSB + kbyte + aRow;
                ldsm4(ah[mt], qaddr);
                ldsm4(al[mt], qaddr + (OFF_QL - OFF_QH));
            }
            #pragma unroll
            for (int ntp = 0; ntp < 2; ntp++) {
                uint32_t kaddr = kbase + (uint32_t)(wn * 32 + ntp * 16) * QKSB + kbyte + bRow;
                uint32_t bh[4], bl[4];
                ldsm4(bh, kaddr);
                ldsm4(bl, kaddr + 9216u);
                #pragma unroll
                for (int mt = 0; mt < 2; mt++) {
                    mma16(cS[mt][2 * ntp],     ah[mt], bh[0], bh[1]);
                    mma16(cS[mt][2 * ntp],     al[mt], bh[0], bh[1]);
                    mma16(cS[mt][2 * ntp],     ah[mt], bl[0], bl[1]);
                    mma16(cS[mt][2 * ntp + 1], ah[mt], bh[2], bh[3]);
                    mma16(cS[mt][2 * ntp + 1], al[mt], bh[2], bh[3]);
                    mma16(cS[mt][2 * ntp + 1], ah[mt], bl[2], bl[3]);
                }
            }
        }

        // ---- warp-local partial row max ----
        float pm[2][2];
        #pragma unroll
        for (int mt = 0; mt < 2; mt++) {
            float m0 = -1e30f, m1 = -1e30f;
            #pragma unroll
            for (int nt = 0; nt < 4; nt++) {
                m0 = fmaxf(m0, fmaxf(cS[mt][nt][0], cS[mt][nt][1]));
                m1 = fmaxf(m1, fmaxf(cS[mt][nt][2], cS[mt][nt][3]));
            }
            m0 = fmaxf(m0, __shfl_xor_sync(0xffffffffu, m0, 1));
            m0 = fmaxf(m0, __shfl_xor_sync(0xffffffffu, m0, 2));
            m1 = fmaxf(m1, __shfl_xor_sync(0xffffffffu, m1, 1));
            m1 = fmaxf(m1, __shfl_xor_sync(0xffffffffu, m1, 2));
            pm[mt][0] = m0; pm[mt][1] = m1;
        }
        if (c4 == 0) {
            #pragma unroll
            for (int mt = 0; mt < 2; mt++) {
                int r = mrow + mt * 16 + r4;
                pmax[wn * 128 + r]     = pm[mt][0];
                pmax[wn * 128 + r + 8] = pm[mt][1];
            }
        }
        // PAIR barrier: only the 2 N-warps sharing these rows (64 threads)
        asm volatile("bar.sync %0, 64;" :: "r"(1 + wm) : "memory");

        // ---- prefetch K(jt+1) into alt buffer ----
        if (jt < 63) {
            int j0n = (jt + 1) << 6;
            uint32_t kdst = sb + OFF_K + (uint32_t)((jt + 1) & 1) * KBUFB;
            #pragma unroll
            for (int i = 0; i < 4; i++) {
                int m = tid + i * 256;
                int r = (m & 511) >> 3, j = m & 7;
                if (m < 512)
                    cp16(kdst + (uint32_t)(r * QKSB + j * 16), &g_Kh[p][j0n + r][j * 8]);
                else
                    cp16(kdst + 9216u + (uint32_t)(r * QKSB + j * 16), &g_Kl[p][j0n + r][j * 8]);
            }
            CP_COMMIT();
        }

        // ---- combined max, alpha (base-2), O-rescale ----
        float m_new[2][2], alpha[2][2];
        #pragma unroll
        for (int mt = 0; mt < 2; mt++) {
            #pragma unroll
            for (int h = 0; h < 2; h++) {
                int r = mrow + mt * 16 + r4 + 8 * h;
                float mt_tile = fmaxf(pmax[r], pmax[128 + r]);
                m_new[mt][h] = fmaxf(m_run[mt][h], mt_tile);
                alpha[mt][h] = exp2f(m_run[mt][h] - m_new[mt][h]);
                m_run[mt][h] = m_new[mt][h];
            }
        }
        bool anyr = (alpha[0][0] < 1.f) | (alpha[0][1] < 1.f)
                  | (alpha[1][0] < 1.f) | (alpha[1][1] < 1.f);
        if (__any_sync(0xffffffffu, anyr)) {
            #pragma unroll
            for (int mt = 0; mt < 2; mt++)
                #pragma unroll
                for (int nt = 0; nt < 16; nt++) {
                    O[mt][nt][0] *= alpha[mt][0];
                    O[mt][nt][1] *= alpha[mt][0];
                    O[mt][nt][2] *= alpha[mt][1];
                    O[mt][nt][3] *= alpha[mt][1];
                }
        }

        // ---- exp2 via f16x2 MUFU, pack fp16 P (regs + smem) ----
        uint32_t pk[2][4][2];
        #pragma unroll
        for (int mt = 0; mt < 2; mt++) {
            int r = mrow + mt * 16 + r4;
            float s0 = 0.f, s1 = 0.f;
            #pragma unroll
            for (int nt = 0; nt < 4; nt++) {
                int col = wn * 32 + nt * 8 + 2 * c4;
                __half2 x01 = __floats2half2_rn(cS[mt][nt][0] - m_new[mt][0],
                                                cS[mt][nt][1] - m_new[mt][0]);
                __half2 x23 = __floats2half2_rn(cS[mt][nt][2] - m_new[mt][1],
                                                cS[mt][nt][3] - m_new[mt][1]);
                __half2 p01 = h2exp2(x01);
                __half2 p23 = h2exp2(x23);
                float2 f01 = __half22float2(p01);
                float2 f23 = __half22float2(p23);
                s0 += f01.x + f01.y;
                s1 += f23.x + f23.y;
                pk[mt][nt][0] = *(uint32_t*)&p01;
                pk[mt][nt][1] = *(uint32_t*)&p23;
                *(uint32_t*)(smem + OFF_P + r * QKSB + col * 2)       = pk[mt][nt][0];
                *(uint32_t*)(smem + OFF_P + (r + 8) * QKSB + col * 2) = pk[mt][nt][1];
            }
            lsum[mt][0] = lsum[mt][0] * alpha[mt][0] + s0;
            lsum[mt][1] = lsum[mt][1] * alpha[mt][1] + s1;
        }

        // ---- LOCAL-half PV from registers ----
        #pragma unroll
        for (int lc = 0; lc < 2; lc++) {
            uint32_t kbyte = (uint32_t)((wn * 2 + lc) * 32);
            uint32_t pa0[4] = { pk[0][2 * lc][0], pk[0][2 * lc][1],
                                pk[0][2 * lc + 1][0], pk[0][2 * lc + 1][1] };
            uint32_t pa1[4] = { pk[1][2 * lc][0], pk[1][2 * lc][1],
                                pk[1][2 * lc + 1][0], pk[1][2 * lc + 1][1] };
            #pragma unroll
            for (int ntp = 0; ntp < 8; ntp++) {
                uint32_t vaddr = vbase + (uint32_t)(wn * 128 + ntp * 16) * QKSB + kbyte + bRow;
                uint32_t vb[4];
                ldsm4(vb, vaddr);
                mma16f(O[0][2 * ntp],     pa0, vb[0], vb[1]);
                mma16f(O[1][2 * ntp],     pa1, vb[0], vb[1]);
                mma16f(O[0][2 * ntp + 1], pa0, vb[2], vb[3]);
                mma16f(O[1][2 * ntp + 1], pa1, vb[2], vb[3]);
            }
        }

        CP_WAIT(0);
        __syncthreads();   // sync_C: partner P visible; K(jt+1)/V(jt+1) published

        // ---- CROSS-half PV from smem P ----
        #pragma unroll
        for (int lc = 0; lc < 2; lc++) {
            uint32_t kbyte = (uint32_t)(((1 - wn) * 2 + lc) * 32);
            uint32_t pa[2][4];
            #pragma unroll
            for (int mt = 0; mt < 2; mt++) {
                uint32_t paddr = sb + OFF_P + (uint32_t)(mrow + mt * 16) * QKSB + kbyte + aRow;
                ldsm4(pa[mt], paddr);
            }
            #pragma unroll
            for (int ntp = 0; ntp < 8; ntp++) {
                uint32_t vaddr = vbase + (uint32_t)(wn * 128 + ntp * 16) * QKSB + kbyte + bRow;
                uint32_t vb[4];
                ldsm4(vb, vaddr);
                mma16f(O[0][2 * ntp],     pa[0], vb[0], vb[1]);
                mma16f(O[1][2 * ntp],     pa[1], vb[0], vb[1]);
                mma16f(O[0][2 * ntp + 1], pa[0], vb[2], vb[3]);
                mma16f(O[1][2 * ntp + 1], pa[1], vb[2], vb[3]);
            }
        }

        vc = vn;
    }

    // ---- row-sum reduction ----
    #pragma unroll
    for (int mt = 0; mt < 2; mt++)
        #pragma unroll
        for (int h = 0; h < 2; h++) {
            float v = lsum[mt][h];
            v += __shfl_xor_sync(0xffffffffu, v, 1);
            v += __shfl_xor_sync(0xffffffffu, v, 2);
            if (c4 == 0) atomicAdd(&lrow[mrow + mt * 16 + r4 + 8 * h], v);
        }
    __syncthreads();

    // ---- epilogue ----
    float gm = gamma[0];
    int s = p >> 1, b = p & 1;
    const float* xin = (s ? in2 : in1) + (size_t)b * CC * NPIX;
    float* o = out + (size_t)p * CC * NPIX;
    #pragma unroll
    for (int mt = 0; mt < 2; mt++) {
        int rlo = mrow + mt * 16 + r4, rhi = rlo + 8;
        float sclo = gm / lrow[rlo];
        float schi = gm / lrow[rhi];
        size_t nlo = (size_t)(i0 + rlo), nhi = (size_t)(i0 + rhi);
        #pragma unroll
        for (int nt = 0; nt < 16; nt++) {
            int ch = wn * 128 + nt * 8 + 2 * c4;
            o[(size_t)ch * NPIX + nlo]       = O[mt][nt][0] * sclo + xin[(size_t)ch * NPIX + nlo];
            o[(size_t)(ch + 1) * NPIX + nlo] = O[mt][nt][1] * sclo + xin[(size_t)(ch + 1) * NPIX + nlo];
            o[(size_t)ch * NPIX + nhi]       = O[mt][nt][2] * schi + xin[(size_t)ch * NPIX + nhi];
            o[(size_t)(ch + 1) * NPIX + nhi] = O[mt][nt][3] * schi + xin[(size_t)(ch + 1) * NPIX + nhi];
        }
    }
}

// ---------------------------------------------------------------------------
extern "C" void kernel_launch(void* const* d_in, const int* in_sizes, int n_in,
                              void* d_out, int out_size)
{
    const float* in1 = (const float*)d_in[0];
    const float* in2 = (const float*)d_in[1];
    const float* q1w = (const float*)d_in[2];  const float* q1b = (const float*)d_in[3];
    const float* k1w = (const float*)d_in[4];  const float* k1b = (const float*)d_in[5];
    const float* v1w = (const float*)d_in[6];  const float* v1b = (const float*)d_in[7];
    const float* q2w = (const float*)d_in[8];  const float* q2b = (const float*)d_in[9];
    const float* k2w = (const float*)d_in[10]; const float* k2b = (const float*)d_in[11];
    const float* v2w = (const float*)d_in[12]; const float* v2b = (const float*)d_in[13];
    const float* gamma = (const float*)d_in[22];
    float* out = (float*)d_out;

    prep_and_convert<<<1792, 256>>>(in1, in2,
                                    q1w, q1b, k1w, k1b, v1w, v1b,
                                    q2w, q2b, k2w, k2b, v2w, v2b);

    cudaFuncSetAttribute(proj_mma, cudaFuncAttributeMaxDynamicSharedMemorySize, (int)PSMEM);
    proj_mma<<<dim3(32, 3, 4), 256, PSMEM>>>();

    cudaFuncSetAttribute(flash_attn, cudaFuncAttributeMaxDynamicSharedMemorySize, (int)SMEM_TOTAL);
    flash_attn<<<dim3(32, 4), 256, SMEM_TOTAL>>>(in1, in2, gamma, out);
}

// round 16
// speedup vs baseline: 1.0769x; 1.0769x over previous
#include <cuda_runtime.h>
#include <cuda_bf16.h>
#include <cuda_fp16.h>
#include <cstdint>

#define CC    256
#define CQ    64
#define NPIX  4096
#define NPAIR 4
#define LOG2E 1.4426950408889634f

// ---------------- helpers ----------------
__device__ __forceinline__ uint32_t smem_u32(const void* p) {
    uint32_t a;
    asm("{ .reg .u64 t; cvta.to.shared.u64 t, %1; cvt.u32.u64 %0, t; }" : "=r"(a) : "l"(p));
    return a;
}

__device__ __forceinline__ void cp16(uint32_t s, const void* g) {
    asm volatile("cp.async.cg.shared.global [%0], [%1], 16;" :: "r"(s), "l"(g) : "memory");
}
#define CP_COMMIT()  asm volatile("cp.async.commit_group;" ::: "memory")
#define CP_WAIT(N)   asm volatile("cp.async.wait_group %0;" :: "n"(N) : "memory")

// ldmatrix x4: four 8x8 b16 matrices -> 4 regs
__device__ __forceinline__ void ldsm4(uint32_t r[4], uint32_t addr) {
    asm volatile("ldmatrix.sync.aligned.m8n8.x4.shared.b16 {%0,%1,%2,%3}, [%4];"
        : "=r"(r[0]), "=r"(r[1]), "=r"(r[2]), "=r"(r[3]) : "r"(addr));
}

// m16n8k16 bf16 mma (S phase + proj)
__device__ __forceinline__ void mma16(float c[4], const uint32_t a[4], uint32_t b0, uint32_t b1) {
    asm volatile(
        "mma.sync.aligned.m16n8k16.row.col.f32.bf16.bf16.f32 "
        "{%0,%1,%2,%3}, {%4,%5,%6,%7}, {%8,%9}, {%0,%1,%2,%3};"
        : "+f"(c[0]), "+f"(c[1]), "+f"(c[2]), "+f"(c[3])
        : "r"(a[0]), "r"(a[1]), "r"(a[2]), "r"(a[3]), "r"(b0), "r"(b1));
}

// m16n8k16 fp16 mma (PV phase)
__device__ __forceinline__ void mma16f(float c[4], const uint32_t a[4], uint32_t b0, uint32_t b1) {
    asm volatile(
        "mma.sync.aligned.m16n8k16.row.col.f32.f16.f16.f32 "
        "{%0,%1,%2,%3}, {%4,%5,%6,%7}, {%8,%9}, {%0,%1,%2,%3};"
        : "+f"(c[0]), "+f"(c[1]), "+f"(c[2]), "+f"(c[3])
        : "r"(a[0]), "r"(a[1]), "r"(a[2]), "r"(a[3]), "r"(b0), "r"(b1));
}

__device__ __forceinline__ uint32_t pack_bf16(float a, float b) {
    __nv_bfloat16 h0 = __float2bfloat16(a), h1 = __float2bfloat16(b);
    uint16_t u0 = *(uint16_t*)&h0, u1 = *(uint16_t*)&h1;
    return ((uint32_t)u1 << 16) | u0;
}

__device__ __forceinline__ uint32_t pack_f16(float a, float b) {
    __half2 h = __floats2half2_rn(a, b);
    return *(uint32_t*)&h;
}

// ---------------- scratch ----------------
__device__ float g_Bias[2][384];
__device__ __nv_bfloat16 g_Wh[2][384][CC];
__device__ __nv_bfloat16 g_Wl[2][384][CC];
__device__ __nv_bfloat16 g_Xh[NPAIR][NPIX][CC];
__device__ __nv_bfloat16 g_Xl[NPAIR][NPIX][CC];
__device__ __nv_bfloat16 g_Qh[NPAIR][NPIX][CQ];   // scaled by log2(e)
__device__ __nv_bfloat16 g_Ql[NPAIR][NPIX][CQ];
__device__ __nv_bfloat16 g_Kh[NPAIR][NPIX][CQ];
__device__ __nv_bfloat16 g_Kl[NPAIR][NPIX][CQ];
__device__ __half g_V[NPAIR][CC][NPIX];           // channel-major fp16 V

// ---------------------------------------------------------------------------
// Merged prep (weights split) + convert (input transpose/split), one launch.
//   blocks [0, 1024)    : convert_x work  (nb 64, cb 4, p 4)
//   blocks [1024, 1792) : prep_weights work (o 384, s 2)
// ---------------------------------------------------------------------------
__global__ __launch_bounds__(256) void prep_and_convert(
    const float* __restrict__ in1, const float* __restrict__ in2,
    const float* __restrict__ q1w, const float* __restrict__ q1b,
    const float* __restrict__ k1w, const float* __restrict__ k1b,
    const float* __restrict__ v1w, const float* __restrict__ v1b,
    const float* __restrict__ q2w, const float* __restrict__ q2b,
    const float* __restrict__ k2w, const float* __restrict__ k2b,
    const float* __restrict__ v2w, const float* __restrict__ v2b)
{
    __shared__ float t[64][65];
    int bx = blockIdx.x;
    int tid = threadIdx.x;

    if (bx >= 1024) {
        int idx = bx - 1024;
        int s = idx / 384, o = idx - s * 384;
        const float* w; const float* bsrc; int row;
        if (o < 64)       { w = s ? q2w : q1w; bsrc = s ? q2b : q1b; row = o; }
        else if (o < 128) { w = s ? k2w : k1w; bsrc = s ? k2b : k1b; row = o - 64; }
        else              { w = s ? v2w : v1w; bsrc = s ? v2b : v1b; row = o - 128; }
        float v = w[row * CC + tid];
        __nv_bfloat16 h = __float2bfloat16(v);
        g_Wh[s][o][tid] = h;
        g_Wl[s][o][tid] = __float2bfloat16(v - __bfloat162float(h));
        if (tid == 0) g_Bias[s][o] = bsrc[row];
        return;
    }

    int nb = bx & 63, cb4 = (bx >> 6) & 3, p = bx >> 8;
    int s = p >> 1, b = p & 1;
    const float* x = (s ? in2 : in1) + (size_t)b * CC * NPIX;
    int n0 = nb * 64, c0 = cb4 * 64;

    #pragma unroll
    for (int i = 0; i < 4; i++) {
        int m = tid + i * 256;
        int c = m >> 4, nn = (m & 15) << 2;
        float4 v = *(const float4*)&x[(size_t)(c0 + c) * NPIX + n0 + nn];
        t[c][nn] = v.x; t[c][nn + 1] = v.y; t[c][nn + 2] = v.z; t[c][nn + 3] = v.w;
    }
    __syncthreads();

    int n = tid >> 2, cb = (tid & 3) << 4;
    uint32_t hw[8], lw[8];
    #pragma unroll
    for (int j = 0; j < 8; j++) {
        float v0 = t[cb + 2 * j][n], v1 = t[cb + 2 * j + 1][n];
        __nv_bfloat16 h0 = __float2bfloat16(v0);
        __nv_bfloat16 h1 = __float2bfloat16(v1);
        float l0 = v0 - __bfloat162float(h0);
        float l1 = v1 - __bfloat162float(h1);
        uint16_t a0 = *(uint16_t*)&h0, a1 = *(uint16_t*)&h1;
        hw[j] = ((uint32_t)a1 << 16) | a0;
        lw[j] = pack_bf16(l0, l1);
    }
    uint4* dh = (uint4*)&g_Xh[p][n0 + n][c0 + cb];
    uint4* dl = (uint4*)&g_Xl[p][n0 + n][c0 + cb];
    dh[0] = make_uint4(hw[0], hw[1], hw[2], hw[3]);
    dh[1] = make_uint4(hw[4], hw[5], hw[6], hw[7]);
    dl[0] = make_uint4(lw[0], lw[1], lw[2], lw[3]);
    dl[1] = make_uint4(lw[4], lw[5], lw[6], lw[7]);
}

// ---------------------------------------------------------------------------
// Tensorized projection; Q epilogue pre-scales by log2(e) for base-2 softmax.
// ---------------------------------------------------------------------------
#define PJS 144u
#define PA_H 0u
#define PA_L 18432u
#define PB_H 36864u
#define PB_L 55296u
#define PSTAGE 73728u
#define POFF_BIAS 147456u
#define PSMEM 147968u

__global__ __launch_bounds__(256, 1) void proj_mma()
{
    extern __shared__ __align__(16) char psm[];
    uint32_t sb = smem_u32(psm);
    float* bias = (float*)(psm + POFF_BIAS);
    int tid = threadIdx.x;
    int p = blockIdx.z, s = p >> 1;
    int n0 = blockIdx.x * 128, o0 = blockIdx.y * 128;
    int warp = tid >> 5, lane = tid & 31;
    int wm = warp >> 1, wn = warp & 1;
    int r4 = lane >> 2, c4 = lane & 3;

    if (tid < 128) bias[tid] = g_Bias[s][o0 + tid];

    auto issue = [&](int kc) {
        uint32_t st = sb + (uint32_t)(kc & 1) * PSTAGE;
        int k0 = kc * 64;
        #pragma unroll
        for (int i = 0; i < 4; i++) {
            int m = tid + i * 256;
            int r = m >> 3, j = m & 7;
            uint32_t off = (uint32_t)r * PJS + (uint32_t)j * 16u;
            cp16(st + PA_H + off, &g_Xh[p][n0 + r][k0 + j * 8]);
            cp16(st + PA_L + off, &g_Xl[p][n0 + r][k0 + j * 8]);
            cp16(st + PB_H + off, &g_Wh[s][o0 + r][k0 + j * 8]);
            cp16(st + PB_L + off, &g_Wl[s][o0 + r][k0 + j * 8]);
        }
        CP_COMMIT();
    };
    issue(0);
    issue(1);

    float cS[2][8][4] = {};

    for (int kc = 0; kc < 4; kc++) {
        CP_WAIT(1);
        __syncthreads();
        const char* st = psm + (kc & 1) * PSTAGE;

        #pragma unroll
        for (int kt = 0; kt < 4; kt++) {
            int kb = kt * 32 + c4 * 4;
            uint32_t ah[2][4], al[2][4];
            #pragma unroll
            for (int mt = 0; mt < 2; mt++) {
                int r = wm * 32 + mt * 16 + r4;
                const char* a_h = st + PA_H + r * PJS + kb;
                const char* a_l = st + PA_L + r * PJS + kb;
                ah[mt][0] = *(const uint32_t*)a_h;
                ah[mt][1] = *(const uint32_t*)(a_h + 8 * PJS);
                ah[mt][2] = *(const uint32_t*)(a_h + 16);
                ah[mt][3] = *(const uint32_t*)(a_h + 8 * PJS + 16);
                al[mt][0] = *(const uint32_t*)a_l;
                al[mt][1] = *(const uint32_t*)(a_l + 8 * PJS);
                al[mt][2] = *(const uint32_t*)(a_l + 16);
                al[mt][3] = *(const uint32_t*)(a_l + 8 * PJS + 16);
            }
            #pragma unroll
            for (int nt = 0; nt < 8; nt++) {
                int o = wn * 64 + nt * 8 + r4;
                const char* b_h = st + PB_H + o * PJS + kb;
                const char* b_l = st + PB_L + o * PJS + kb;
                uint32_t bh0 = *(const uint32_t*)b_h;
                uint32_t bh1 = *(const uint32_t*)(b_h + 16);
                uint32_t bl0 = *(const uint32_t*)b_l;
                uint32_t bl1 = *(const uint32_t*)(b_l + 16);
                #pragma unroll
                for (int mt = 0; mt < 2; mt++) {
                    mma16(cS[mt][nt], ah[mt], bh0, bh1);
                    mma16(cS[mt][nt], al[mt], bh0, bh1);
                    mma16(cS[mt][nt], ah[mt], bl0, bl1);
                }
            }
        }
        __syncthreads();
        if (kc < 2) issue(kc + 2);
    }

    #pragma unroll
    for (int mt = 0; mt < 2; mt++) {
        int n_lo = n0 + wm * 32 + mt * 16 + r4;
        int n_hi = n_lo + 8;
        #pragma unroll
        for (int nt = 0; nt < 8; nt++) {
            int ol = wn * 64 + nt * 8 + 2 * c4;
            int og = o0 + ol;
            float b0 = bias[ol], b1 = bias[ol + 1];
            float y00 = cS[mt][nt][0] + b0, y01 = cS[mt][nt][1] + b1;
            float y10 = cS[mt][nt][2] + b0, y11 = cS[mt][nt][3] + b1;
            if (og < 64) {
                y00 *= LOG2E; y01 *= LOG2E; y10 *= LOG2E; y11 *= LOG2E;
                __nv_bfloat16 h00 = __float2bfloat16(y00), h01 = __float2bfloat16(y01);
                __nv_bfloat16 h10 = __float2bfloat16(y10), h11 = __float2bfloat16(y11);
                uint16_t u00 = *(uint16_t*)&h00, u01 = *(uint16_t*)&h01;
                uint16_t u10 = *(uint16_t*)&h10, u11 = *(uint16_t*)&h11;
                *(uint32_t*)&g_Qh[p][n_lo][og] = ((uint32_t)u01 << 16) | u00;
                *(uint32_t*)&g_Qh[p][n_hi][og] = ((uint32_t)u11 << 16) | u10;
                *(uint32_t*)&g_Ql[p][n_lo][og] =
                    pack_bf16(y00 - __bfloat162float(h00), y01 - __bfloat162float(h01));
                *(uint32_t*)&g_Ql[p][n_hi][og] =
                    pack_bf16(y10 - __bfloat162float(h10), y11 - __bfloat162float(h11));
            } else if (og < 128) {
                int oo = og - 64;
                __nv_bfloat16 h00 = __float2bfloat16(y00), h01 = __float2bfloat16(y01);
                __nv_bfloat16 h10 = __float2bfloat16(y10), h11 = __float2bfloat16(y11);
                uint16_t u00 = *(uint16_t*)&h00, u01 = *(uint16_t*)&h01;
                uint16_t u10 = *(uint16_t*)&h10, u11 = *(uint16_t*)&h11;
                *(uint32_t*)&g_Kh[p][n_lo][oo] = ((uint32_t)u01 << 16) | u00;
                *(uint32_t*)&g_Kh[p][n_hi][oo] = ((uint32_t)u11 << 16) | u10;
                *(uint32_t*)&g_Kl[p][n_lo][oo] =
                    pack_bf16(y00 - __bfloat162float(h00), y01 - __bfloat162float(h01));
                *(uint32_t*)&g_Kl[p][n_hi][oo] =
                    pack_bf16(y10 - __bfloat162float(h10), y11 - __bfloat162float(h11));
            } else {
                int c = og - 128;
                g_V[p][c][n_lo]     = __float2half(y00);
                g_V[p][c + 1][n_lo] = __float2half(y01);
                g_V[p][c][n_hi]     = __float2half(y10);
                g_V[p][c + 1][n_hi] = __float2half(y11);
            }
        }
    }
}

// ---------------------------------------------------------------------------
// Flash attention (R14 configuration, verified 181.1 us / rel_err 7.575e-5):
// 128-row tiles, 8 warps (4M x 2N), 1 CTA/SM. ONE full-CTA barrier/tile +
// one PAIR barrier for pmax. K double-buffered, V triple-buffered.
// Base-2 softmax via exp2f. PV: local half from regs, cross half from smem.
// ---------------------------------------------------------------------------
#define QKSB 144
#define KBUFB 18432u
#define OFF_K   0u
#define VBUFB  36864u
#define OFF_V0  36864u
#define OFF_QH 147456u
#define OFF_QL 165888u
#define OFF_P  184320u
#define OFF_L  202752u
#define OFF_PM 203264u
#define SMEM_TOTAL 204288u

__global__ __launch_bounds__(256, 1)
void flash_attn(const float* __restrict__ in1, const float* __restrict__ in2,
                const float* __restrict__ gamma, float* __restrict__ out)
{
    extern __shared__ __align__(16) char smem[];
    float* lrow = (float*)(smem + OFF_L);
    float* pmax = (float*)(smem + OFF_PM);
    uint32_t sb = smem_u32(smem);

    int tid  = threadIdx.x;
    int p    = blockIdx.y;
    int i0   = blockIdx.x * 128;
    int warp = tid >> 5, lane = tid & 31;
    int wm = warp >> 1, wn = warp & 1;       // 4M x 2N
    int r4 = lane >> 2, c4 = lane & 3;
    int lm = lane >> 3, lr = lane & 7;
    int mrow = wm * 32;

    uint32_t aRow = (uint32_t)((lm & 1) * 8 + lr) * QKSB + (uint32_t)((lm >> 1) * 16);
    uint32_t bRow = (uint32_t)((lm >> 1) * 8 + lr) * QKSB + (uint32_t)((lm & 1) * 16);

    if (tid < 128) lrow[tid] = 0.f;

    // ---- prologue: load Q, K(0), V(0); wait; publish ----
    {
        #pragma unroll
        for (int i = 0; i < 8; i++) {
            int m = tid + i * 256;
            int r = (m & 1023) >> 3, j = m & 7;
            if (m < 1024)
                cp16(sb + OFF_QH + (uint32_t)(r * QKSB + j * 16), &g_Qh[p][i0 + r][j * 8]);
            else
                cp16(sb + OFF_QL + (uint32_t)(r * QKSB + j * 16), &g_Ql[p][i0 + r][j * 8]);
        }
        #pragma unroll
        for (int i = 0; i < 4; i++) {
            int m = tid + i * 256;
            int r = (m & 511) >> 3, j = m & 7;
            if (m < 512)
                cp16(sb + OFF_K + (uint32_t)(r * QKSB + j * 16), &g_Kh[p][r][j * 8]);
            else
                cp16(sb + OFF_K + 9216u + (uint32_t)(r * QKSB + j * 16), &g_Kl[p][r][j * 8]);
        }
        #pragma unroll
        for (int i = 0; i < 8; i++) {
            int m = tid + i * 256;
            int ch = m >> 3, j = m & 7;
            cp16(sb + OFF_V0 + (uint32_t)(ch * QKSB + j * 16), &g_V[p][ch][j * 8]);
        }
        CP_COMMIT();
        CP_WAIT(0);
        __syncthreads();
    }

    float O[2][16][4];
    #pragma unroll
    for (int mt = 0; mt < 2; mt++)
        #pragma unroll
        for (int nt = 0; nt < 16; nt++)
            #pragma unroll
            for (int i = 0; i < 4; i++) O[mt][nt][i] = 0.f;

    float lsum[2][2] = {};
    float m_run[2][2] = {{-1e30f, -1e30f}, {-1e30f, -1e30f}};

    int vc = 0;

    for (int jt = 0; jt < 64; jt++) {
        uint32_t kbase = sb + OFF_K  + (uint32_t)(jt & 1) * KBUFB;
        uint32_t vbase = sb + OFF_V0 + (uint32_t)vc * VBUFB;
        int vn = vc + 1; if (vn == 3) vn = 0;

        // ---- prefetch V(jt+1) into third buffer ----
        if (jt < 63) {
            int j0n = (jt + 1) << 6;
            uint32_t vdst = sb + OFF_V0 + (uint32_t)vn * VBUFB;
            #pragma unroll
            for (int i = 0; i < 8; i++) {
                int m = tid + i * 256;
                int ch = m >> 3, j = m & 7;
                cp16(vdst + (uint32_t)(ch * QKSB + j * 16), &g_V[p][ch][j0n + j * 8]);
            }
            CP_COMMIT();
        }

        // ---- S = QK^T: 3-term split-bf16 (ldmatrix); logits in log2 units ----
        float cS[2][4][4];
        #pragma unroll
        for (int mt = 0; mt < 2; mt++)
            #pragma unroll
            for (int nt = 0; nt < 4; nt++)
                #pragma unroll
                for (int i = 0; i < 4; i++) cS[mt][nt][i] = 0.f;

        #pragma unroll
        for (int kt = 0; kt < 4; kt++) {
            uint32_t kbyte = (uint32_t)kt * 32u;
            uint32_t ah[2][4], al[2][4];
            #pragma unroll
            for (int mt = 0; mt < 2; mt++) {
                uint32_t qaddr = sb + OFF_QH + (uint32_t)(mrow + mt * 16) * QKSB + kbyte + aRow;
                ldsm4(ah[mt], qaddr);
                ldsm4(al[mt], qaddr + (OFF_QL - OFF_QH));
            }
            #pragma unroll
            for (int ntp = 0; ntp < 2; ntp++) {
                uint32_t kaddr = kbase + (uint32_t)(wn * 32 + ntp * 16) * QKSB + kbyte + bRow;
                uint32_t bh[4], bl[4];
                ldsm4(bh, kaddr);
                ldsm4(bl, kaddr + 9216u);
                #pragma unroll
                for (int mt = 0; mt < 2; mt++) {
                    mma16(cS[mt][2 * ntp],     ah[mt], bh[0], bh[1]);
                    mma16(cS[mt][2 * ntp],     al[mt], bh[0], bh[1]);
                    mma16(cS[mt][2 * ntp],     ah[mt], bl[0], bl[1]);
                    mma16(cS[mt][2 * ntp + 1], ah[mt], bh[2], bh[3]);
                    mma16(cS[mt][2 * ntp + 1], al[mt], bh[2], bh[3]);
                    mma16(cS[mt][2 * ntp + 1], ah[mt], bl[2], bl[3]);
                }
            }
        }

        // ---- warp-local partial row max ----
        float pm[2][2];
        #pragma unroll
        for (int mt = 0; mt < 2; mt++) {
            float m0 = -1e30f, m1 = -1e30f;
            #pragma unroll
            for (int nt = 0; nt < 4; nt++) {
                m0 = fmaxf(m0, fmaxf(cS[mt][nt][0], cS[mt][nt][1]));
                m1 = fmaxf(m1, fmaxf(cS[mt][nt][2], cS[mt][nt][3]));
            }
            m0 = fmaxf(m0, __shfl_xor_sync(0xffffffffu, m0, 1));
            m0 = fmaxf(m0, __shfl_xor_sync(0xffffffffu, m0, 2));
            m1 = fmaxf(m1, __shfl_xor_sync(0xffffffffu, m1, 1));
            m1 = fmaxf(m1, __shfl_xor_sync(0xffffffffu, m1, 2));
            pm[mt][0] = m0; pm[mt][1] = m1;
        }
        if (c4 == 0) {
            #pragma unroll
            for (int mt = 0; mt < 2; mt++) {
                int r = mrow + mt * 16 + r4;
                pmax[wn * 128 + r]     = pm[mt][0];
                pmax[wn * 128 + r + 8] = pm[mt][1];
            }
        }
        // PAIR barrier: only the 2 N-warps sharing these rows (64 threads)
        asm volatile("bar.sync %0, 64;" :: "r"(1 + wm) : "memory");

        // ---- prefetch K(jt+1) into alt buffer ----
        if (jt < 63) {
            int j0n = (jt + 1) << 6;
            uint32_t kdst = sb + OFF_K + (uint32_t)((jt + 1) & 1) * KBUFB;
            #pragma unroll
            for (int i = 0; i < 4; i++) {
                int m = tid + i * 256;
                int r = (m & 511) >> 3, j = m & 7;
                if (m < 512)
                    cp16(kdst + (uint32_t)(r * QKSB + j * 16), &g_Kh[p][j0n + r][j * 8]);
                else
                    cp16(kdst + 9216u + (uint32_t)(r * QKSB + j * 16), &g_Kl[p][j0n + r][j * 8]);
            }
            CP_COMMIT();
        }

        // ---- combined max, alpha (base-2), O-rescale ----
        float m_new[2][2], alpha[2][2];
        #pragma unroll
        for (int mt = 0; mt < 2; mt++) {
            #pragma unroll
            for (int h = 0; h < 2; h++) {
                int r = mrow + mt * 16 + r4 + 8 * h;
                float mt_tile = fmaxf(pmax[r], pmax[128 + r]);
                m_new[mt][h] = fmaxf(m_run[mt][h], mt_tile);
                alpha[mt][h] = exp2f(m_run[mt][h] - m_new[mt][h]);
                m_run[mt][h] = m_new[mt][h];
            }
        }
        bool anyr = (alpha[0][0] < 1.f) | (alpha[0][1] < 1.f)
                  | (alpha[1][0] < 1.f) | (alpha[1][1] < 1.f);
        if (__any_sync(0xffffffffu, anyr)) {
            #pragma unroll
            for (int mt = 0; mt < 2; mt++)
                #pragma unroll
                for (int nt = 0; nt < 16; nt++) {
                    O[mt][nt][0] *= alpha[mt][0];
                    O[mt][nt][1] *= alpha[mt][0];
                    O[mt][nt][2] *= alpha[mt][1];
                    O[mt][nt][3] *= alpha[mt][1];
                }
        }

        // ---- exp2, pack fp16 P (regs + smem) ----
        uint32_t pk[2][4][2];
        #pragma unroll
        for (int mt = 0; mt < 2; mt++) {
            int r = mrow + mt * 16 + r4;
            float s0 = 0.f, s1 = 0.f;
            #pragma unroll
            for (int nt = 0; nt < 4; nt++) {
                int col = wn * 32 + nt * 8 + 2 * c4;
                float e0 = exp2f(cS[mt][nt][0] - m_new[mt][0]);
                float e1 = exp2f(cS[mt][nt][1] - m_new[mt][0]);
                float e2 = exp2f(cS[mt][nt][2] - m_new[mt][1]);
                float e3 = exp2f(cS[mt][nt][3] - m_new[mt][1]);
                s0 += e0 + e1;
                s1 += e2 + e3;
                pk[mt][nt][0] = pack_f16(e0, e1);
                pk[mt][nt][1] = pack_f16(e2, e3);
                *(uint32_t*)(smem + OFF_P + r * QKSB + col * 2)       = pk[mt][nt][0];
                *(uint32_t*)(smem + OFF_P + (r + 8) * QKSB + col * 2) = pk[mt][nt][1];
            }
            lsum[mt][0] = lsum[mt][0] * alpha[mt][0] + s0;
            lsum[mt][1] = lsum[mt][1] * alpha[mt][1] + s1;
        }

        // ---- LOCAL-half PV from registers ----
        #pragma unroll
        for (int lc = 0; lc < 2; lc++) {
            uint32_t kbyte = (uint32_t)((wn * 2 + lc) * 32);
            uint32_t pa0[4] = { pk[0][2 * lc][0], pk[0][2 * lc][1],
                                pk[0][2 * lc + 1][0], pk[0][2 * lc + 1][1] };
            uint32_t pa1[4] = { pk[1][2 * lc][0], pk[1][2 * lc][1],
                                pk[1][2 * lc + 1][0], pk[1][2 * lc + 1][1] };
            #pragma unroll
            for (int ntp = 0; ntp < 8; ntp++) {
                uint32_t vaddr = vbase + (uint32_t)(wn * 128 + ntp * 16) * QKSB + kbyte + bRow;
                uint32_t vb[4];
                ldsm4(vb, vaddr);
                mma16f(O[0][2 * ntp],     pa0, vb[0], vb[1]);
                mma16f(O[1][2 * ntp],     pa1, vb[0], vb[1]);
                mma16f(O[0][2 * ntp + 1], pa0, vb[2], vb[3]);
                mma16f(O[1][2 * ntp + 1], pa1, vb[2], vb[3]);
            }
        }

        CP_WAIT(0);
        __syncthreads();   // sync_C: partner P visible; K(jt+1)/V(jt+1) published

        // ---- CROSS-half PV from smem P ----
        #pragma unroll
        for (int lc = 0; lc < 2; lc++) {
            uint32_t kbyte = (uint32_t)(((1 - wn) * 2 + lc) * 32);
            uint32_t pa[2][4];
            #pragma unroll
            for (int mt = 0; mt < 2; mt++) {
                uint32_t paddr = sb + OFF_P + (uint32_t)(mrow + mt * 16) * QKSB + kbyte + aRow;
                ldsm4(pa[mt], paddr);
            }
            #pragma unroll
            for (int ntp = 0; ntp < 8; ntp++) {
                uint32_t vaddr = vbase + (uint32_t)(wn * 128 + ntp * 16) * QKSB + kbyte + bRow;
                uint32_t vb[4];
                ldsm4(vb, vaddr);
                mma16f(O[0][2 * ntp],     pa[0], vb[0], vb[1]);
                mma16f(O[1][2 * ntp],     pa[1], vb[0], vb[1]);
                mma16f(O[0][2 * ntp + 1], pa[0], vb[2], vb[3]);
                mma16f(O[1][2 * ntp + 1], pa[1], vb[2], vb[3]);
            }
        }

        vc = vn;
    }

    // ---- row-sum reduction ----
    #pragma unroll
    for (int mt = 0; mt < 2; mt++)
        #pragma unroll
        for (int h = 0; h < 2; h++) {
            float v = lsum[mt][h];
            v += __shfl_xor_sync(0xffffffffu, v, 1);
            v += __shfl_xor_sync(0xffffffffu, v, 2);
            if (c4 == 0) atomicAdd(&lrow[mrow + mt * 16 + r4 + 8 * h], v);
        }
    __syncthreads();

    // ---- epilogue ----
    float gm = gamma[0];
    int s = p >> 1, b = p & 1;
    const float* xin = (s ? in2 : in1) + (size_t)b * CC * NPIX;
    float* o = out + (size_t)p * CC * NPIX;
    #pragma unroll
    for (int mt = 0; mt < 2; mt++) {
        int rlo = mrow + mt * 16 + r4, rhi = rlo + 8;
        float sclo = gm / lrow[rlo];
        float schi = gm / lrow[rhi];
        size_t nlo = (size_t)(i0 + rlo), nhi = (size_t)(i0 + rhi);
        #pragma unroll
        for (int nt = 0; nt < 16; nt++) {
            int ch = wn * 128 + nt * 8 + 2 * c4;
            o[(size_t)ch * NPIX + nlo]       = O[mt][nt][0] * sclo + xin[(size_t)ch * NPIX + nlo];
            o[(size_t)(ch + 1) * NPIX + nlo] = O[mt][nt][1] * sclo + xin[(size_t)(ch + 1) * NPIX + nlo];
            o[(size_t)ch * NPIX + nhi]       = O[mt][nt][2] * schi + xin[(size_t)ch * NPIX + nhi];
            o[(size_t)(ch + 1) * NPIX + nhi] = O[mt][nt][3] * schi + xin[(size_t)(ch + 1) * NPIX + nhi];
        }
    }
}

// ---------------------------------------------------------------------------
extern "C" void kernel_launch(void* const* d_in, const int* in_sizes, int n_in,
                              void* d_out, int out_size)
{
    const float* in1 = (const float*)d_in[0];
    const float* in2 = (const float*)d_in[1];
    const float* q1w = (const float*)d_in[2];  const float* q1b = (const float*)d_in[3];
    const float* k1w = (const float*)d_in[4];  const float* k1b = (const float*)d_in[5];
    const float* v1w = (const float*)d_in[6];  const float* v1b = (const float*)d_in[7];
    const float* q2w = (const float*)d_in[8];  const float* q2b = (const float*)d_in[9];
    const float* k2w = (const float*)d_in[10]; const float* k2b = (const float*)d_in[11];
    const float* v2w = (const float*)d_in[12]; const float* v2b = (const float*)d_in[13];
    const float* gamma = (const float*)d_in[22];
    float* out = (float*)d_out;

    prep_and_convert<<<1792, 256>>>(in1, in2,
                                    q1w, q1b, k1w, k1b, v1w, v1b,
                                    q2w, q2b, k2w, k2b, v2w, v2b);

    cudaFuncSetAttribute(proj_mma, cudaFuncAttributeMaxDynamicSharedMemorySize, (int)PSMEM);
    proj_mma<<<dim3(32, 3, 4), 256, PSMEM>>>();

    cudaFuncSetAttribute(flash_attn, cudaFuncAttributeMaxDynamicSharedMemorySize, (int)SMEM_TOTAL);
    flash_attn<<<dim3(32, 4), 256, SMEM_TOTAL>>>(in1, in2, gamma, out);
}

// round 17
// speedup vs baseline: 1.0856x; 1.0080x over previous
#include <cuda_runtime.h>
#include <cuda_bf16.h>
#include <cuda_fp16.h>
#include <cstdint>

#define CC    256
#define CQ    64
#define NPIX  4096
#define NPAIR 4
#define LOG2E 1.4426950408889634f

// ---------------- helpers ----------------
__device__ __forceinline__ uint32_t smem_u32(const void* p) {
    uint32_t a;
    asm("{ .reg .u64 t; cvta.to.shared.u64 t, %1; cvt.u32.u64 %0, t; }" : "=r"(a) : "l"(p));
    return a;
}

__device__ __forceinline__ void cp16(uint32_t s, const void* g) {
    asm volatile("cp.async.cg.shared.global [%0], [%1], 16;" :: "r"(s), "l"(g) : "memory");
}
#define CP_COMMIT()  asm volatile("cp.async.commit_group;" ::: "memory")
#define CP_WAIT(N)   asm volatile("cp.async.wait_group %0;" :: "n"(N) : "memory")

// ldmatrix x4: four 8x8 b16 matrices -> 4 regs
__device__ __forceinline__ void ldsm4(uint32_t r[4], uint32_t addr) {
    asm volatile("ldmatrix.sync.aligned.m8n8.x4.shared.b16 {%0,%1,%2,%3}, [%4];"
        : "=r"(r[0]), "=r"(r[1]), "=r"(r[2]), "=r"(r[3]) : "r"(addr));
}

// m16n8k16 bf16 mma (S phase + proj)
__device__ __forceinline__ void mma16(float c[4], const uint32_t a[4], uint32_t b0, uint32_t b1) {
    asm volatile(
        "mma.sync.aligned.m16n8k16.row.col.f32.bf16.bf16.f32 "
        "{%0,%1,%2,%3}, {%4,%5,%6,%7}, {%8,%9}, {%0,%1,%2,%3};"
        : "+f"(c[0]), "+f"(c[1]), "+f"(c[2]), "+f"(c[3])
        : "r"(a[0]), "r"(a[1]), "r"(a[2]), "r"(a[3]), "r"(b0), "r"(b1));
}

// m16n8k16 fp16 mma (PV phase)
__device__ __forceinline__ void mma16f(float c[4], const uint32_t a[4], uint32_t b0, uint32_t b1) {
    asm volatile(
        "mma.sync.aligned.m16n8k16.row.col.f32.f16.f16.f32 "
        "{%0,%1,%2,%3}, {%4,%5,%6,%7}, {%8,%9}, {%0,%1,%2,%3};"
        : "+f"(c[0]), "+f"(c[1]), "+f"(c[2]), "+f"(c[3])
        : "r"(a[0]), "r"(a[1]), "r"(a[2]), "r"(a[3]), "r"(b0), "r"(b1));
}

__device__ __forceinline__ uint32_t pack_bf16(float a, float b) {
    __nv_bfloat16 h0 = __float2bfloat16(a), h1 = __float2bfloat16(b);
    uint16_t u0 = *(uint16_t*)&h0, u1 = *(uint16_t*)&h1;
    return ((uint32_t)u1 << 16) | u0;
}

__device__ __forceinline__ uint32_t pack_f16(float a, float b) {
    __half2 h = __floats2half2_rn(a, b);
    return *(uint32_t*)&h;
}

// ---------------- scratch ----------------
__device__ float g_Bias[2][384];
__device__ __nv_bfloat16 g_Wh[2][384][CC];
__device__ __nv_bfloat16 g_Wl[2][384][CC];
__device__ __nv_bfloat16 g_Xh[NPAIR][NPIX][CC];
__device__ __nv_bfloat16 g_Xl[NPAIR][NPIX][CC];
__device__ __nv_bfloat16 g_Qh[NPAIR][NPIX][CQ];   // scaled by log2(e)
__device__ __nv_bfloat16 g_Ql[NPAIR][NPIX][CQ];
__device__ __nv_bfloat16 g_Kh[NPAIR][NPIX][CQ];
__device__ __nv_bfloat16 g_Kl[NPAIR][NPIX][CQ];
__device__ __half g_V[NPAIR][CC][NPIX];           // channel-major fp16 V

// ---------------------------------------------------------------------------
// Merged prep (weights split) + convert (input transpose/split), one launch.
// ---------------------------------------------------------------------------
__global__ __launch_bounds__(256) void prep_and_convert(
    const float* __restrict__ in1, const float* __restrict__ in2,
    const float* __restrict__ q1w, const float* __restrict__ q1b,
    const float* __restrict__ k1w, const float* __restrict__ k1b,
    const float* __restrict__ v1w, const float* __restrict__ v1b,
    const float* __restrict__ q2w, const float* __restrict__ q2b,
    const float* __restrict__ k2w, const float* __restrict__ k2b,
    const float* __restrict__ v2w, const float* __restrict__ v2b)
{
    __shared__ float t[64][65];
    int bx = blockIdx.x;
    int tid = threadIdx.x;

    if (bx >= 1024) {
        int idx = bx - 1024;
        int s = idx / 384, o = idx - s * 384;
        const float* w; const float* bsrc; int row;
        if (o < 64)       { w = s ? q2w : q1w; bsrc = s ? q2b : q1b; row = o; }
        else if (o < 128) { w = s ? k2w : k1w; bsrc = s ? k2b : k1b; row = o - 64; }
        else              { w = s ? v2w : v1w; bsrc = s ? v2b : v1b; row = o - 128; }
        float v = w[row * CC + tid];
        __nv_bfloat16 h = __float2bfloat16(v);
        g_Wh[s][o][tid] = h;
        g_Wl[s][o][tid] = __float2bfloat16(v - __bfloat162float(h));
        if (tid == 0) g_Bias[s][o] = bsrc[row];
        return;
    }

    int nb = bx & 63, cb4 = (bx >> 6) & 3, p = bx >> 8;
    int s = p >> 1, b = p & 1;
    const float* x = (s ? in2 : in1) + (size_t)b * CC * NPIX;
    int n0 = nb * 64, c0 = cb4 * 64;

    #pragma unroll
    for (int i = 0; i < 4; i++) {
        int m = tid + i * 256;
        int c = m >> 4, nn = (m & 15) << 2;
        float4 v = *(const float4*)&x[(size_t)(c0 + c) * NPIX + n0 + nn];
        t[c][nn] = v.x; t[c][nn + 1] = v.y; t[c][nn + 2] = v.z; t[c][nn + 3] = v.w;
    }
    __syncthreads();

    int n = tid >> 2, cb = (tid & 3) << 4;
    uint32_t hw[8], lw[8];
    #pragma unroll
    for (int j = 0; j < 8; j++) {
        float v0 = t[cb + 2 * j][n], v1 = t[cb + 2 * j + 1][n];
        __nv_bfloat16 h0 = __float2bfloat16(v0);
        __nv_bfloat16 h1 = __float2bfloat16(v1);
        float l0 = v0 - __bfloat162float(h0);
        float l1 = v1 - __bfloat162float(h1);
        uint16_t a0 = *(uint16_t*)&h0, a1 = *(uint16_t*)&h1;
        hw[j] = ((uint32_t)a1 << 16) | a0;
        lw[j] = pack_bf16(l0, l1);
    }
    uint4* dh = (uint4*)&g_Xh[p][n0 + n][c0 + cb];
    uint4* dl = (uint4*)&g_Xl[p][n0 + n][c0 + cb];
    dh[0] = make_uint4(hw[0], hw[1], hw[2], hw[3]);
    dh[1] = make_uint4(hw[4], hw[5], hw[6], hw[7]);
    dl[0] = make_uint4(lw[0], lw[1], lw[2], lw[3]);
    dl[1] = make_uint4(lw[4], lw[5], lw[6], lw[7]);
}

// ---------------------------------------------------------------------------
// Tensorized projection: 3-stage cp.async pipeline, ONE barrier per k-chunk,
// ldmatrix fragment loads. Q epilogue pre-scales by log2(e).
// ---------------------------------------------------------------------------
#define PJS 144u
#define PA_H 0u
#define PA_L 18432u
#define PB_H 36864u
#define PB_L 55296u
#define PSTAGE 73728u
#define POFF_BIAS (3u * PSTAGE)          // 221184
#define PSMEM (POFF_BIAS + 512u)         // 221696

__global__ __launch_bounds__(256, 1) void proj_mma()
{
    extern __shared__ __align__(16) char psm[];
    uint32_t sb = smem_u32(psm);
    float* bias = (float*)(psm + POFF_BIAS);
    int tid = threadIdx.x;
    int p = blockIdx.z, s = p >> 1;
    int n0 = blockIdx.x * 128, o0 = blockIdx.y * 128;
    int warp = tid >> 5, lane = tid & 31;
    int wm = warp >> 1, wn = warp & 1;
    int r4 = lane >> 2, c4 = lane & 3;
    int lm = lane >> 3, lr = lane & 7;

    uint32_t aRow = (uint32_t)((lm & 1) * 8 + lr) * PJS + (uint32_t)((lm >> 1) * 16);
    uint32_t bRow = (uint32_t)((lm >> 1) * 8 + lr) * PJS + (uint32_t)((lm & 1) * 16);

    if (tid < 128) bias[tid] = g_Bias[s][o0 + tid];

    auto issue = [&](int kc) {
        uint32_t st = sb + (uint32_t)(kc % 3) * PSTAGE;
        int k0 = kc * 64;
        #pragma unroll
        for (int i = 0; i < 4; i++) {
            int m = tid + i * 256;
            int r = m >> 3, j = m & 7;
            uint32_t off = (uint32_t)r * PJS + (uint32_t)j * 16u;
            cp16(st + PA_H + off, &g_Xh[p][n0 + r][k0 + j * 8]);
            cp16(st + PA_L + off, &g_Xl[p][n0 + r][k0 + j * 8]);
            cp16(st + PB_H + off, &g_Wh[s][o0 + r][k0 + j * 8]);
            cp16(st + PB_L + off, &g_Wl[s][o0 + r][k0 + j * 8]);
        }
        CP_COMMIT();
    };
    issue(0); issue(1); issue(2);

    float cS[2][8][4] = {};

    auto do_mma = [&](uint32_t st) {
        #pragma unroll
        for (int kt = 0; kt < 4; kt++) {
            uint32_t kbyte = (uint32_t)kt * 32u;
            uint32_t ah[2][4], al[2][4];
            #pragma unroll
            for (int mt = 0; mt < 2; mt++) {
                uint32_t aaddr = st + PA_H + (uint32_t)(wm * 32 + mt * 16) * PJS + kbyte + aRow;
                ldsm4(ah[mt], aaddr);
                ldsm4(al[mt], aaddr + (PA_L - PA_H));
            }
            #pragma unroll
            for (int ntp = 0; ntp < 4; ntp++) {
                uint32_t baddr = st + PB_H + (uint32_t)(wn * 64 + ntp * 16) * PJS + kbyte + bRow;
                uint32_t bh[4], bl[4];
                ldsm4(bh, baddr);
                ldsm4(bl, baddr + (PB_L - PB_H));
                #pragma unroll
                for (int mt = 0; mt < 2; mt++) {
                    mma16(cS[mt][2 * ntp],     ah[mt], bh[0], bh[1]);
                    mma16(cS[mt][2 * ntp],     al[mt], bh[0], bh[1]);
                    mma16(cS[mt][2 * ntp],     ah[mt], bl[0], bl[1]);
                    mma16(cS[mt][2 * ntp + 1], ah[mt], bh[2], bh[3]);
                    mma16(cS[mt][2 * ntp + 1], al[mt], bh[2], bh[3]);
                    mma16(cS[mt][2 * ntp + 1], ah[mt], bl[2], bl[3]);
                }
            }
        }
    };

    // kc=0: grp0 done (3 committed, completed>=1)
    CP_WAIT(2); __syncthreads();
    do_mma(sb + 0u * PSTAGE);
    // kc=1: grp1 done (completed>=2); all warps past mma(stage0) -> issue(3) into stage0
    CP_WAIT(1); __syncthreads();
    issue(3);
    do_mma(sb + 1u * PSTAGE);
    // kc=2: grp2 done (4 committed, completed>=3)
    CP_WAIT(1); __syncthreads();
    do_mma(sb + 2u * PSTAGE);
    // kc=3: grp3 done
    CP_WAIT(0); __syncthreads();
    do_mma(sb + 0u * PSTAGE);

    #pragma unroll
    for (int mt = 0; mt < 2; mt++) {
        int n_lo = n0 + wm * 32 + mt * 16 + r4;
        int n_hi = n_lo + 8;
        #pragma unroll
        for (int nt = 0; nt < 8; nt++) {
            int ol = wn * 64 + nt * 8 + 2 * c4;
            int og = o0 + ol;
            float b0 = bias[ol], b1 = bias[ol + 1];
            float y00 = cS[mt][nt][0] + b0, y01 = cS[mt][nt][1] + b1;
            float y10 = cS[mt][nt][2] + b0, y11 = cS[mt][nt][3] + b1;
            if (og < 64) {
                y00 *= LOG2E; y01 *= LOG2E; y10 *= LOG2E; y11 *= LOG2E;
                __nv_bfloat16 h00 = __float2bfloat16(y00), h01 = __float2bfloat16(y01);
                __nv_bfloat16 h10 = __float2bfloat16(y10), h11 = __float2bfloat16(y11);
                uint16_t u00 = *(uint16_t*)&h00, u01 = *(uint16_t*)&h01;
                uint16_t u10 = *(uint16_t*)&h10, u11 = *(uint16_t*)&h11;
                *(uint32_t*)&g_Qh[p][n_lo][og] = ((uint32_t)u01 << 16) | u00;
                *(uint32_t*)&g_Qh[p][n_hi][og] = ((uint32_t)u11 << 16) | u10;
                *(uint32_t*)&g_Ql[p][n_lo][og] =
                    pack_bf16(y00 - __bfloat162float(h00), y01 - __bfloat162float(h01));
                *(uint32_t*)&g_Ql[p][n_hi][og] =
                    pack_bf16(y10 - __bfloat162float(h10), y11 - __bfloat162float(h11));
            } else if (og < 128) {
                int oo = og - 64;
                __nv_bfloat16 h00 = __float2bfloat16(y00), h01 = __float2bfloat16(y01);
                __nv_bfloat16 h10 = __float2bfloat16(y10), h11 = __float2bfloat16(y11);
                uint16_t u00 = *(uint16_t*)&h00, u01 = *(uint16_t*)&h01;
                uint16_t u10 = *(uint16_t*)&h10, u11 = *(uint16_t*)&h11;
                *(uint32_t*)&g_Kh[p][n_lo][oo] = ((uint32_t)u01 << 16) | u00;
                *(uint32_t*)&g_Kh[p][n_hi][oo] = ((uint32_t)u11 << 16) | u10;
                *(uint32_t*)&g_Kl[p][n_lo][oo] =
                    pack_bf16(y00 - __bfloat162float(h00), y01 - __bfloat162float(h01));
                *(uint32_t*)&g_Kl[p][n_hi][oo] =
                    pack_bf16(y10 - __bfloat162float(h10), y11 - __bfloat162float(h11));
            } else {
                int c = og - 128;
                g_V[p][c][n_lo]     = __float2half(y00);
                g_V[p][c + 1][n_lo] = __float2half(y01);
                g_V[p][c][n_hi]     = __float2half(y10);
                g_V[p][c + 1][n_hi] = __float2half(y11);
            }
        }
    }
}

// ---------------------------------------------------------------------------
// Flash attention (R14/R16 configuration, unchanged).
// ---------------------------------------------------------------------------
#define QKSB 144
#define KBUFB 18432u
#define OFF_K   0u
#define VBUFB  36864u
#define OFF_V0  36864u
#define OFF_QH 147456u
#define OFF_QL 165888u
#define OFF_P  184320u
#define OFF_L  202752u
#define OFF_PM 203264u
#define SMEM_TOTAL 204288u

__global__ __launch_bounds__(256, 1)
void flash_attn(const float* __restrict__ in1, const float* __restrict__ in2,
                const float* __restrict__ gamma, float* __restrict__ out)
{
    extern __shared__ __align__(16) char smem[];
    float* lrow = (float*)(smem + OFF_L);
    float* pmax = (float*)(smem + OFF_PM);
    uint32_t sb = smem_u32(smem);

    int tid  = threadIdx.x;
    int p    = blockIdx.y;
    int i0   = blockIdx.x * 128;
    int warp = tid >> 5, lane = tid & 31;
    int wm = warp >> 1, wn = warp & 1;
    int r4 = lane >> 2, c4 = lane & 3;
    int lm = lane >> 3, lr = lane & 7;
    int mrow = wm * 32;

    uint32_t aRow = (uint32_t)((lm & 1) * 8 + lr) * QKSB + (uint32_t)((lm >> 1) * 16);
    uint32_t bRow = (uint32_t)((lm >> 1) * 8 + lr) * QKSB + (uint32_t)((lm & 1) * 16);

    if (tid < 128) lrow[tid] = 0.f;

    {
        #pragma unroll
        for (int i = 0; i < 8; i++) {
            int m = tid + i * 256;
            int r = (m & 1023) >> 3, j = m & 7;
            if (m < 1024)
                cp16(sb + OFF_QH + (uint32_t)(r * QKSB + j * 16), &g_Qh[p][i0 + r][j * 8]);
            else
                cp16(sb + OFF_QL + (uint32_t)(r * QKSB + j * 16), &g_Ql[p][i0 + r][j * 8]);
        }
        #pragma unroll
        for (int i = 0; i < 4; i++) {
            int m = tid + i * 256;
            int r = (m & 511) >> 3, j = m & 7;
            if (m < 512)
                cp16(sb + OFF_K + (uint32_t)(r * QKSB + j * 16), &g_Kh[p][r][j * 8]);
            else
                cp16(sb + OFF_K + 9216u + (uint32_t)(r * QKSB + j * 16), &g_Kl[p][r][j * 8]);
        }
        #pragma unroll
        for (int i = 0; i < 8; i++) {
            int m = tid + i * 256;
            int ch = m >> 3, j = m & 7;
            cp16(sb + OFF_V0 + (uint32_t)(ch * QKSB + j * 16), &g_V[p][ch][j * 8]);
        }
        CP_COMMIT();
        CP_WAIT(0);
        __syncthreads();
    }

    float O[2][16][4];
    #pragma unroll
    for (int mt = 0; mt < 2; mt++)
        #pragma unroll
        for (int nt = 0; nt < 16; nt++)
            #pragma unroll
            for (int i = 0; i < 4; i++) O[mt][nt][i] = 0.f;

    float lsum[2][2] = {};
    float m_run[2][2] = {{-1e30f, -1e30f}, {-1e30f, -1e30f}};

    int vc = 0;

    for (int jt = 0; jt < 64; jt++) {
        uint32_t kbase = sb + OFF_K  + (uint32_t)(jt & 1) * KBUFB;
        uint32_t vbase = sb + OFF_V0 + (uint32_t)vc * VBUFB;
        int vn = vc + 1; if (vn == 3) vn = 0;

        if (jt < 63) {
            int j0n = (jt + 1) << 6;
            uint32_t vdst = sb + OFF_V0 + (uint32_t)vn * VBUFB;
            #pragma unroll
            for (int i = 0; i < 8; i++) {
                int m = tid + i * 256;
                int ch = m >> 3, j = m & 7;
                cp16(vdst + (uint32_t)(ch * QKSB + j * 16), &g_V[p][ch][j0n + j * 8]);
            }
            CP_COMMIT();
        }

        float cS[2][4][4];
        #pragma unroll
        for (int mt = 0; mt < 2; mt++)
            #pragma unroll
            for (int nt = 0; nt < 4; nt++)
                #pragma unroll
                for (int i = 0; i < 4; i++) cS[mt][nt][i] = 0.f;

        #pragma unroll
        for (int kt = 0; kt < 4; kt++) {
            uint32_t kbyte = (uint32_t)kt * 32u;
            uint32_t ah[2][4], al[2][4];
            #pragma unroll
            for (int mt = 0; mt < 2; mt++) {
                uint32_t qaddr = sb + OFF_QH + (uint32_t)(mrow + mt * 16) * QKSB + kbyte + aRow;
                ldsm4(ah[mt], qaddr);
                ldsm4(al[mt], qaddr + (OFF_QL - OFF_QH));
            }
            #pragma unroll
            for (int ntp = 0; ntp < 2; ntp++) {
                uint32_t kaddr = kbase + (uint32_t)(wn * 32 + ntp * 16) * QKSB + kbyte + bRow;
                uint32_t bh[4], bl[4];
                ldsm4(bh, kaddr);
                ldsm4(bl, kaddr + 9216u);
                #pragma unroll
                for (int mt = 0; mt < 2; mt++) {
                    mma16(cS[mt][2 * ntp],     ah[mt], bh[0], bh[1]);
                    mma16(cS[mt][2 * ntp],     al[mt], bh[0], bh[1]);
                    mma16(cS[mt][2 * ntp],     ah[mt], bl[0], bl[1]);
                    mma16(cS[mt][2 * ntp + 1], ah[mt], bh[2], bh[3]);
                    mma16(cS[mt][2 * ntp + 1], al[mt], bh[2], bh[3]);
                    mma16(cS[mt][2 * ntp + 1], ah[mt], bl[2], bl[3]);
                }
            }
        }

        float pm[2][2];
        #pragma unroll
        for (int mt = 0; mt < 2; mt++) {
            float m0 = -1e30f, m1 = -1e30f;
            #pragma unroll
            for (int nt = 0; nt < 4; nt++) {
                m0 = fmaxf(m0, fmaxf(cS[mt][nt][0], cS[mt][nt][1]));
                m1 = fmaxf(m1, fmaxf(cS[mt][nt][2], cS[mt][nt][3]));
            }
            m0 = fmaxf(m0, __shfl_xor_sync(0xffffffffu, m0, 1));
            m0 = fmaxf(m0, __shfl_xor_sync(0xffffffffu, m0, 2));
            m1 = fmaxf(m1, __shfl_xor_sync(0xffffffffu, m1, 1));
            m1 = fmaxf(m1, __shfl_xor_sync(0xffffffffu, m1, 2));
            pm[mt][0] = m0; pm[mt][1] = m1;
        }
        if (c4 == 0) {
            #pragma unroll
            for (int mt = 0; mt < 2; mt++) {
                int r = mrow + mt * 16 + r4;
                pmax[wn * 128 + r]     = pm[mt][0];
                pmax[wn * 128 + r + 8] = pm[mt][1];
            }
        }
        asm volatile("bar.sync %0, 64;" :: "r"(1 + wm) : "memory");

        if (jt < 63) {
            int j0n = (jt + 1) << 6;
            uint32_t kdst = sb + OFF_K + (uint32_t)((jt + 1) & 1) * KBUFB;
            #pragma unroll
            for (int i = 0; i < 4; i++) {
                int m = tid + i * 256;
                int r = (m & 511) >> 3, j = m & 7;
                if (m < 512)
                    cp16(kdst + (uint32_t)(r * QKSB + j * 16), &g_Kh[p][j0n + r][j * 8]);
                else
                    cp16(kdst + 9216u + (uint32_t)(r * QKSB + j * 16), &g_Kl[p][j0n + r][j * 8]);
            }
            CP_COMMIT();
        }

        float m_new[2][2], alpha[2][2];
        #pragma unroll
        for (int mt = 0; mt < 2; mt++) {
            #pragma unroll
            for (int h = 0; h < 2; h++) {
                int r = mrow + mt * 16 + r4 + 8 * h;
                float mt_tile = fmaxf(pmax[r], pmax[128 + r]);
                m_new[mt][h] = fmaxf(m_run[mt][h], mt_tile);
                alpha[mt][h] = exp2f(m_run[mt][h] - m_new[mt][h]);
                m_run[mt][h] = m_new[mt][h];
            }
        }
        bool anyr = (alpha[0][0] < 1.f) | (alpha[0][1] < 1.f)
                  | (alpha[1][0] < 1.f) | (alpha[1][1] < 1.f);
        if (__any_sync(0xffffffffu, anyr)) {
            #pragma unroll
            for (int mt = 0; mt < 2; mt++)
                #pragma unroll
                for (int nt = 0; nt < 16; nt++) {
                    O[mt][nt][0] *= alpha[mt][0];
                    O[mt][nt][1] *= alpha[mt][0];
                    O[mt][nt][2] *= alpha[mt][1];
                    O[mt][nt][3] *= alpha[mt][1];
                }
        }

        uint32_t pk[2][4][2];
        #pragma unroll
        for (int mt = 0; mt < 2; mt++) {
            int r = mrow + mt * 16 + r4;
            float s0 = 0.f, s1 = 0.f;
            #pragma unroll
            for (int nt = 0; nt < 4; nt++) {
                int col = wn * 32 + nt * 8 + 2 * c4;
                float e0 = exp2f(cS[mt][nt][0] - m_new[mt][0]);
                float e1 = exp2f(cS[mt][nt][1] - m_new[mt][0]);
                float e2 = exp2f(cS[mt][nt][2] - m_new[mt][1]);
                float e3 = exp2f(cS[mt][nt][3] - m_new[mt][1]);
                s0 += e0 + e1;
                s1 += e2 + e3;
                pk[mt][nt][0] = pack_f16(e0, e1);
                pk[mt][nt][1] = pack_f16(e2, e3);
                *(uint32_t*)(smem + OFF_P + r * QKSB + col * 2)       = pk[mt][nt][0];
                *(uint32_t*)(smem + OFF_P + (r + 8) * QKSB + col * 2) = pk[mt][nt][1];
            }
            lsum[mt][0] = lsum[mt][0] * alpha[mt][0] + s0;
            lsum[mt][1] = lsum[mt][1] * alpha[mt][1] + s1;
        }

        #pragma unroll
        for (int lc = 0; lc < 2; lc++) {
            uint32_t kbyte = (uint32_t)((wn * 2 + lc) * 32);
            uint32_t pa0[4] = { pk[0][2 * lc][0], pk[0][2 * lc][1],
                                pk[0][2 * lc + 1][0], pk[0][2 * lc + 1][1] };
            uint32_t pa1[4] = { pk[1][2 * lc][0], pk[1][2 * lc][1],
                                pk[1][2 * lc + 1][0], pk[1][2 * lc + 1][1] };
            #pragma unroll
            for (int ntp = 0; ntp < 8; ntp++) {
                uint32_t vaddr = vbase + (uint32_t)(wn * 128 + ntp * 16) * QKSB + kbyte + bRow;
                uint32_t vb[4];
                ldsm4(vb, vaddr);
                mma16f(O[0][2 * ntp],     pa0, vb[0], vb[1]);
                mma16f(O[1][2 * ntp],     pa1, vb[0], vb[1]);
                mma16f(O[0][2 * ntp + 1], pa0, vb[2], vb[3]);
                mma16f(O[1][2 * ntp + 1], pa1, vb[2], vb[3]);
            }
        }

        CP_WAIT(0);
        __syncthreads();

        #pragma unroll
        for (int lc = 0; lc < 2; lc++) {
            uint32_t kbyte = (uint32_t)(((1 - wn) * 2 + lc) * 32);
            uint32_t pa[2][4];
            #pragma unroll
            for (int mt = 0; mt < 2; mt++) {
                uint32_t paddr = sb + OFF_P + (uint32_t)(mrow + mt * 16) * QKSB + kbyte + aRow;
                ldsm4(pa[mt], paddr);
            }
            #pragma unroll
            for (int ntp = 0; ntp < 8; ntp++) {
                uint32_t vaddr = vbase + (uint32_t)(wn * 128 + ntp * 16) * QKSB + kbyte + bRow;
                uint32_t vb[4];
                ldsm4(vb, vaddr);
                mma16f(O[0][2 * ntp],     pa[0], vb[0], vb[1]);
                mma16f(O[1][2 * ntp],     pa[1], vb[0], vb[1]);
                mma16f(O[0][2 * ntp + 1], pa[0], vb[2], vb[3]);
                mma16f(O[1][2 * ntp + 1], pa[1], vb[2], vb[3]);
            }
        }

        vc = vn;
    }

    #pragma unroll
    for (int mt = 0; mt < 2; mt++)
        #pragma unroll
        for (int h = 0; h < 2; h++) {
            float v = lsum[mt][h];
            v += __shfl_xor_sync(0xffffffffu, v, 1);
            v += __shfl_xor_sync(0xffffffffu, v, 2);
            if (c4 == 0) atomicAdd(&lrow[mrow + mt * 16 + r4 + 8 * h], v);
        }
    __syncthreads();

    float gm = gamma[0];
    int s = p >> 1, b = p & 1;
    const float* xin = (s ? in2 : in1) + (size_t)b * CC * NPIX;
    float* o = out + (size_t)p * CC * NPIX;
    #pragma unroll
    for (int mt = 0; mt < 2; mt++) {
        int rlo = mrow + mt * 16 + r4, rhi = rlo + 8;
        float sclo = gm / lrow[rlo];
        float schi = gm / lrow[rhi];
        size_t nlo = (size_t)(i0 + rlo), nhi = (size_t)(i0 + rhi);
        #pragma unroll
        for (int nt = 0; nt < 16; nt++) {
            int ch = wn * 128 + nt * 8 + 2 * c4;
            o[(size_t)ch * NPIX + nlo]       = O[mt][nt][0] * sclo + xin[(size_t)ch * NPIX + nlo];
            o[(size_t)(ch + 1) * NPIX + nlo] = O[mt][nt][1] * sclo + xin[(size_t)(ch + 1) * NPIX + nlo];
            o[(size_t)ch * NPIX + nhi]       = O[mt][nt][2] * schi + xin[(size_t)ch * NPIX + nhi];
            o[(size_t)(ch + 1) * NPIX + nhi] = O[mt][nt][3] * schi + xin[(size_t)(ch + 1) * NPIX + nhi];
        }
    }
}

// ---------------------------------------------------------------------------
extern "C" void kernel_launch(void* const* d_in, const int* in_sizes, int n_in,
                              void* d_out, int out_size)
{
    const float* in1 = (const float*)d_in[0];
    const float* in2 = (const float*)d_in[1];
    const float* q1w = (const float*)d_in[2];  const float* q1b = (const float*)d_in[3];
    const float* k1w = (const float*)d_in[4];  const float* k1b = (const float*)d_in[5];
    const float* v1w = (const float*)d_in[6];  const float* v1b = (const float*)d_in[7];
    const float* q2w = (const float*)d_in[8];  const float* q2b = (const float*)d_in[9];
    const float* k2w = (const float*)d_in[10]; const float* k2b = (const float*)d_in[11];
    const float* v2w = (const float*)d_in[12]; const float* v2b = (const float*)d_in[13];
    const float* gamma = (const float*)d_in[22];
    float* out = (float*)d_out;

    prep_and_convert<<<1792, 256>>>(in1, in2,
                                    q1w, q1b, k1w, k1b, v1w, v1b,
                                    q2w, q2b, k2w, k2b, v2w, v2b);

    cudaFuncSetAttribute(proj_mma, cudaFuncAttributeMaxDynamicSharedMemorySize, (int)PSMEM);
    proj_mma<<<dim3(32, 3, 4), 256, PSMEM>>>();

    cudaFuncSetAttribute(flash_attn, cudaFuncAttributeMaxDynamicSharedMemorySize, (int)SMEM_TOTAL);
    flash_attn<<<dim3(32, 4), 256, SMEM_TOTAL>>>(in1, in2, gamma, out);
}